// round 1
// baseline (speedup 1.0000x reference)
#include <cuda_runtime.h>
#include <cuda_bf16.h>
#include <cstdint>

#define TDIM 8192
#define DDIM 4096

// ---- device scratch (allocation-free rule: __device__ globals) ----
static __device__ __nv_bfloat16 g_w1[(size_t)DDIM * DDIM];
static __device__ __nv_bfloat16 g_w2[(size_t)DDIM * DDIM];
static __device__ __nv_bfloat16 g_ahi[(size_t)TDIM * DDIM];
static __device__ __nv_bfloat16 g_alo[(size_t)TDIM * DDIM];
static __device__ __nv_bfloat16 g_hhi[(size_t)TDIM * DDIM];
static __device__ __nv_bfloat16 g_hlo[(size_t)TDIM * DDIM];

__constant__ float c_lut[16] = {0.f, 0.5f, 1.f, 1.5f, 2.f, 3.f, 4.f, 6.f,
                                -0.f, -0.5f, -1.f, -1.5f, -2.f, -3.f, -4.f, -6.f};

// ---- dequant: int32 codes [D,D] * 2^scales [D,D/32] -> bf16 [D,D] ----
__global__ void dequant_kernel(const int* __restrict__ codes,
                               const float* __restrict__ scales,
                               int which) {
    __nv_bfloat16* __restrict__ out = which ? g_w2 : g_w1;
    size_t base = ((size_t)blockIdx.x * blockDim.x + threadIdx.x) * 4;
    int4 c = *reinterpret_cast<const int4*>(codes + base);
    size_t o = base >> 12;                 // / 4096
    int i = (int)(base & 4095);
    float s = __ldg(scales + o * (DDIM / 32) + (i >> 5));
    __nv_bfloat162 p0, p1;
    p0.x = __float2bfloat16(c_lut[c.x & 15] * s);
    p0.y = __float2bfloat16(c_lut[c.y & 15] * s);
    p1.x = __float2bfloat16(c_lut[c.z & 15] * s);
    p1.y = __float2bfloat16(c_lut[c.w & 15] * s);
    *reinterpret_cast<__nv_bfloat162*>(out + base) = p0;
    *reinterpret_cast<__nv_bfloat162*>(out + base + 2) = p1;
}

// ---- split fp32 x into bf16 hi + bf16 lo residual ----
__global__ void split_kernel(const float* __restrict__ x) {
    size_t base = ((size_t)blockIdx.x * blockDim.x + threadIdx.x) * 4;
    float4 v = *reinterpret_cast<const float4*>(x + base);
    __nv_bfloat16 h0 = __float2bfloat16(v.x);
    __nv_bfloat16 h1 = __float2bfloat16(v.y);
    __nv_bfloat16 h2 = __float2bfloat16(v.z);
    __nv_bfloat16 h3 = __float2bfloat16(v.w);
    __nv_bfloat162 hp0, hp1, lp0, lp1;
    hp0.x = h0; hp0.y = h1; hp1.x = h2; hp1.y = h3;
    lp0.x = __float2bfloat16(v.x - __bfloat162float(h0));
    lp0.y = __float2bfloat16(v.y - __bfloat162float(h1));
    lp1.x = __float2bfloat16(v.z - __bfloat162float(h2));
    lp1.y = __float2bfloat16(v.w - __bfloat162float(h3));
    *reinterpret_cast<__nv_bfloat162*>(g_ahi + base) = hp0;
    *reinterpret_cast<__nv_bfloat162*>(g_ahi + base + 2) = hp1;
    *reinterpret_cast<__nv_bfloat162*>(g_alo + base) = lp0;
    *reinterpret_cast<__nv_bfloat162*>(g_alo + base + 2) = lp1;
}

__device__ __forceinline__ void ldmat4(uint32_t addr, uint32_t& d0, uint32_t& d1,
                                       uint32_t& d2, uint32_t& d3) {
    asm volatile("ldmatrix.sync.aligned.m8n8.x4.shared.b16 {%0,%1,%2,%3}, [%4];\n"
                 : "=r"(d0), "=r"(d1), "=r"(d2), "=r"(d3) : "r"(addr));
}

__device__ __forceinline__ void mma16816(float* c, const uint32_t* a, const uint32_t* b) {
    asm volatile(
        "mma.sync.aligned.m16n8k16.row.col.f32.bf16.bf16.f32 "
        "{%0,%1,%2,%3}, {%4,%5,%6,%7}, {%8,%9}, {%0,%1,%2,%3};\n"
        : "+f"(c[0]), "+f"(c[1]), "+f"(c[2]), "+f"(c[3])
        : "r"(a[0]), "r"(a[1]), "r"(a[2]), "r"(a[3]), "r"(b[0]), "r"(b[1]));
}

// ---- GEMM: out[t,o] = sum_k (Ahi+Alo)[t,k] * W[o,k] + bias[o] ----
// LAYER 0: reads g_ahi/g_alo/g_w1, writes g_hhi/g_hlo (bf16 hi/lo split)
// LAYER 1: reads g_hhi/g_hlo/g_w2, writes fp32 outf
template <int LAYER>
__global__ void __launch_bounds__(256, 1)
gemm_kernel(const float* __restrict__ bias, float* __restrict__ outf) {
    const __nv_bfloat16* __restrict__ Ahi = (LAYER == 0) ? g_ahi : g_hhi;
    const __nv_bfloat16* __restrict__ Alo = (LAYER == 0) ? g_alo : g_hlo;
    const __nv_bfloat16* __restrict__ W = (LAYER == 0) ? g_w1 : g_w2;

    __shared__ __align__(16) __nv_bfloat16 sW[128 * 40];
    __shared__ __align__(16) __nv_bfloat16 sHi[128 * 40];
    __shared__ __align__(16) __nv_bfloat16 sLo[128 * 40];

    const int tid = threadIdx.x;
    const int lane = tid & 31;
    const int wid = tid >> 5;
    const int wm = wid & 1;   // 2 warps along M
    const int wn = wid >> 1;  // 4 warps along N
    const int t0 = blockIdx.y * 128;
    const int o0 = blockIdx.x * 128;

    // global -> smem loading map: 2 threads per row, 16 cols each
    const int lrow = tid >> 1;
    const int lcol = (tid & 1) * 16;
    const __nv_bfloat16* gW = W + (size_t)(o0 + lrow) * DDIM + lcol;
    const __nv_bfloat16* gHi = Ahi + (size_t)(t0 + lrow) * DDIM + lcol;
    const __nv_bfloat16* gLo = Alo + (size_t)(t0 + lrow) * DDIM + lcol;

    float acc[4][4][4];
#pragma unroll
    for (int i = 0; i < 4; i++)
#pragma unroll
        for (int j = 0; j < 4; j++)
#pragma unroll
            for (int k = 0; k < 4; k++) acc[i][j][k] = 0.f;

    const uint32_t sW32 = (uint32_t)__cvta_generic_to_shared(sW);
    const uint32_t sHi32 = (uint32_t)__cvta_generic_to_shared(sHi);
    const uint32_t sLo32 = (uint32_t)__cvta_generic_to_shared(sLo);

    // ldmatrix lane address components
    const int aRow = lane & 15;              // A: rows 0..15
    const int aColB = (lane >> 4) * 8;       // A: k-block 0 / 8
    const int bRow = (lane & 7) + ((lane >> 4) << 3);  // B: n within 16-block
    const int bColB = ((lane >> 3) & 1) * 8;           // B: k-block 0 / 8

    const int stOff = lrow * 40 + lcol;

    uint4 rW0, rW1, rH0, rH1, rL0, rL1;
    rW0 = *reinterpret_cast<const uint4*>(gW);
    rW1 = *reinterpret_cast<const uint4*>(gW + 8);
    rH0 = *reinterpret_cast<const uint4*>(gHi);
    rH1 = *reinterpret_cast<const uint4*>(gHi + 8);
    rL0 = *reinterpret_cast<const uint4*>(gLo);
    rL1 = *reinterpret_cast<const uint4*>(gLo + 8);

    for (int k0 = 0; k0 < DDIM; k0 += 32) {
        // commit prefetched tile to smem
        *reinterpret_cast<uint4*>(sW + stOff) = rW0;
        *reinterpret_cast<uint4*>(sW + stOff + 8) = rW1;
        *reinterpret_cast<uint4*>(sHi + stOff) = rH0;
        *reinterpret_cast<uint4*>(sHi + stOff + 8) = rH1;
        *reinterpret_cast<uint4*>(sLo + stOff) = rL0;
        *reinterpret_cast<uint4*>(sLo + stOff + 8) = rL1;
        __syncthreads();

        // prefetch next tile into registers (hide gmem latency under mma)
        if (k0 + 32 < DDIM) {
            gW += 32; gHi += 32; gLo += 32;
            rW0 = *reinterpret_cast<const uint4*>(gW);
            rW1 = *reinterpret_cast<const uint4*>(gW + 8);
            rH0 = *reinterpret_cast<const uint4*>(gHi);
            rH1 = *reinterpret_cast<const uint4*>(gHi + 8);
            rL0 = *reinterpret_cast<const uint4*>(gLo);
            rL1 = *reinterpret_cast<const uint4*>(gLo + 8);
        }

#pragma unroll
        for (int kk = 0; kk < 32; kk += 16) {
            // B fragments for warp's 32 N columns: two x4 ldmatrix (16 n each)
            uint32_t b[4][2];
#pragma unroll
            for (int nb = 0; nb < 2; nb++) {
                uint32_t addr =
                    sW32 + (uint32_t)(((wn * 32 + nb * 16 + bRow) * 40 + kk + bColB) * 2);
                ldmat4(addr, b[nb * 2][0], b[nb * 2][1], b[nb * 2 + 1][0], b[nb * 2 + 1][1]);
            }
            uint32_t a[4][4];
            // hi pass
#pragma unroll
            for (int mf = 0; mf < 4; mf++) {
                uint32_t addr =
                    sHi32 + (uint32_t)(((wm * 64 + mf * 16 + aRow) * 40 + kk + aColB) * 2);
                ldmat4(addr, a[mf][0], a[mf][1], a[mf][2], a[mf][3]);
            }
#pragma unroll
            for (int mf = 0; mf < 4; mf++)
#pragma unroll
                for (int nf = 0; nf < 4; nf++) mma16816(acc[mf][nf], a[mf], b[nf]);
            // lo pass (same accumulators)
#pragma unroll
            for (int mf = 0; mf < 4; mf++) {
                uint32_t addr =
                    sLo32 + (uint32_t)(((wm * 64 + mf * 16 + aRow) * 40 + kk + aColB) * 2);
                ldmat4(addr, a[mf][0], a[mf][1], a[mf][2], a[mf][3]);
            }
#pragma unroll
            for (int mf = 0; mf < 4; mf++)
#pragma unroll
                for (int nf = 0; nf < 4; nf++) mma16816(acc[mf][nf], a[mf], b[nf]);
        }
        __syncthreads();
    }

    // epilogue
    const int gr = lane >> 2;
    const int tc = lane & 3;
#pragma unroll
    for (int mf = 0; mf < 4; mf++) {
#pragma unroll
        for (int nf = 0; nf < 4; nf++) {
            int row0 = t0 + wm * 64 + mf * 16 + gr;
            int col = o0 + wn * 32 + nf * 8 + tc * 2;
            float bv0 = __ldg(bias + col);
            float bv1 = __ldg(bias + col + 1);
            float v00 = acc[mf][nf][0] + bv0;
            float v01 = acc[mf][nf][1] + bv1;
            float v10 = acc[mf][nf][2] + bv0;
            float v11 = acc[mf][nf][3] + bv1;
            if (LAYER == 0) {
                __nv_bfloat16 h00 = __float2bfloat16(v00);
                __nv_bfloat16 h01 = __float2bfloat16(v01);
                __nv_bfloat16 h10 = __float2bfloat16(v10);
                __nv_bfloat16 h11 = __float2bfloat16(v11);
                __nv_bfloat162 hp0, hp1, lp0, lp1;
                hp0.x = h00; hp0.y = h01;
                hp1.x = h10; hp1.y = h11;
                lp0.x = __float2bfloat16(v00 - __bfloat162float(h00));
                lp0.y = __float2bfloat16(v01 - __bfloat162float(h01));
                lp1.x = __float2bfloat16(v10 - __bfloat162float(h10));
                lp1.y = __float2bfloat16(v11 - __bfloat162float(h11));
                size_t p0 = (size_t)row0 * DDIM + col;
                size_t p1 = (size_t)(row0 + 8) * DDIM + col;
                *reinterpret_cast<__nv_bfloat162*>(g_hhi + p0) = hp0;
                *reinterpret_cast<__nv_bfloat162*>(g_hlo + p0) = lp0;
                *reinterpret_cast<__nv_bfloat162*>(g_hhi + p1) = hp1;
                *reinterpret_cast<__nv_bfloat162*>(g_hlo + p1) = lp1;
            } else {
                float2 o0v = make_float2(v00, v01);
                float2 o1v = make_float2(v10, v11);
                *reinterpret_cast<float2*>(outf + (size_t)row0 * DDIM + col) = o0v;
                *reinterpret_cast<float2*>(outf + (size_t)(row0 + 8) * DDIM + col) = o1v;
            }
        }
    }
}

extern "C" void kernel_launch(void* const* d_in, const int* in_sizes, int n_in,
                              void* d_out, int out_size) {
    const float* x = (const float*)d_in[0];
    const int* w1c = (const int*)d_in[1];
    const float* w1s = (const float*)d_in[2];
    const float* b1 = (const float*)d_in[3];
    const int* w2c = (const int*)d_in[4];
    const float* w2s = (const float*)d_in[5];
    const float* b2 = (const float*)d_in[6];
    float* out = (float*)d_out;

    // dequant both weight matrices: D*D/4 threads
    const int dq_blocks = (DDIM * (size_t)DDIM / 4) / 256;
    dequant_kernel<<<dq_blocks, 256>>>(w1c, w1s, 0);
    dequant_kernel<<<dq_blocks, 256>>>(w2c, w2s, 1);

    // split x into hi/lo bf16
    const int sp_blocks = ((size_t)TDIM * DDIM / 4) / 256;
    split_kernel<<<sp_blocks, 256>>>(x);

    dim3 grid(DDIM / 128, TDIM / 128);
    gemm_kernel<0><<<grid, 256>>>(b1, nullptr);
    gemm_kernel<1><<<grid, 256>>>(b2, out);
}

// round 3
// speedup vs baseline: 2.1428x; 2.1428x over previous
#include <cuda_runtime.h>
#include <cuda_fp16.h>
#include <cstdint>

#define TDIM 8192
#define DDIM 4096

// ---- device scratch (allocation-free rule: __device__ globals) ----
static __device__ __half g_w1[(size_t)DDIM * DDIM];
static __device__ __half g_w2[(size_t)DDIM * DDIM];
static __device__ __half g_a[(size_t)TDIM * DDIM];
static __device__ __half g_h[(size_t)TDIM * DDIM];

__constant__ float c_lut[16] = {0.f, 0.5f, 1.f, 1.5f, 2.f, 3.f, 4.f, 6.f,
                                -0.f, -0.5f, -1.f, -1.5f, -2.f, -3.f, -4.f, -6.f};

// ---- dequant: int32 codes [D,D] * 2^scales [D,D/32] -> fp16 [D,D] (exact) ----
__global__ void dequant_kernel(const int* __restrict__ codes,
                               const float* __restrict__ scales,
                               int which) {
    __half* __restrict__ out = which ? g_w2 : g_w1;
    size_t base = ((size_t)blockIdx.x * blockDim.x + threadIdx.x) * 4;
    int4 c = *reinterpret_cast<const int4*>(codes + base);
    size_t o = base >> 12;
    int i = (int)(base & 4095);
    float s = __ldg(scales + o * (DDIM / 32) + (i >> 5));
    __half2 p0 = __floats2half2_rn(c_lut[c.x & 15] * s, c_lut[c.y & 15] * s);
    __half2 p1 = __floats2half2_rn(c_lut[c.z & 15] * s, c_lut[c.w & 15] * s);
    *reinterpret_cast<__half2*>(out + base) = p0;
    *reinterpret_cast<__half2*>(out + base + 2) = p1;
}

// ---- convert fp32 x -> fp16 ----
__global__ void split_kernel(const float* __restrict__ x) {
    size_t base = ((size_t)blockIdx.x * blockDim.x + threadIdx.x) * 4;
    float4 v = *reinterpret_cast<const float4*>(x + base);
    *reinterpret_cast<__half2*>(g_a + base) = __floats2half2_rn(v.x, v.y);
    *reinterpret_cast<__half2*>(g_a + base + 2) = __floats2half2_rn(v.z, v.w);
}

__device__ __forceinline__ void ldmat4(uint32_t addr, uint32_t& d0, uint32_t& d1,
                                       uint32_t& d2, uint32_t& d3) {
    asm volatile("ldmatrix.sync.aligned.m8n8.x4.shared.b16 {%0,%1,%2,%3}, [%4];\n"
                 : "=r"(d0), "=r"(d1), "=r"(d2), "=r"(d3) : "r"(addr));
}

__device__ __forceinline__ void mma16816(float* c, const uint32_t* a, const uint32_t* b) {
    asm volatile(
        "mma.sync.aligned.m16n8k16.row.col.f32.f16.f16.f32 "
        "{%0,%1,%2,%3}, {%4,%5,%6,%7}, {%8,%9}, {%0,%1,%2,%3};\n"
        : "+f"(c[0]), "+f"(c[1]), "+f"(c[2]), "+f"(c[3])
        : "r"(a[0]), "r"(a[1]), "r"(a[2]), "r"(a[3]), "r"(b[0]), "r"(b[1]));
}

// XOR-swizzled smem offset (bytes): 64B rows of 4x16B chunks; conflict-free
// for both STS.128 and ldmatrix with chunk ^= (row>>1)&3.
__device__ __forceinline__ uint32_t swoff(int row, int kchunk) {
    return (uint32_t)(row * 64 + ((kchunk ^ ((row >> 1) & 3)) << 4));
}

// ---- GEMM: out[t,o] = sum_k A[t,k] * W[o,k] + bias[o] ----
// CTA tile 128(M) x 256(N), K-chunk 32. 8 warps = 2(M) x 4(N), 64x64 each.
template <int LAYER>
__global__ void __launch_bounds__(256, 1)
gemm_kernel(const float* __restrict__ bias, float* __restrict__ outf) {
    const __half* __restrict__ A = (LAYER == 0) ? g_a : g_h;
    const __half* __restrict__ W = (LAYER == 0) ? g_w1 : g_w2;

    __shared__ float sBias[256];
    __shared__ __align__(128) __half sW[256 * 32];
    __shared__ __align__(128) __half sA[128 * 32];

    const int tid = threadIdx.x;
    const int lane = tid & 31;
    const int wid = tid >> 5;
    const int wm = wid & 1;   // 2 warps along M (64 rows each)
    const int wn = wid >> 1;  // 4 warps along N (64 cols each)
    const int o0 = blockIdx.x * 256;
    const int t0 = blockIdx.y * 128;

    sBias[tid] = __ldg(bias + o0 + tid);

    // loader map: thread -> (row r0 + 64*i, 16B chunk c) within tile
    const int r0 = tid >> 2;
    const int c = tid & 3;
    const int cc = c * 8;  // halves
    const __half* gW = W + (size_t)(o0 + r0) * DDIM + cc;
    const __half* gA = A + (size_t)(t0 + r0) * DDIM + cc;
    // swizzled STS offsets (xor term constant across i since 64 rows -> (row>>1)&3 unchanged... 64>>1=32, &3=0)
    uint32_t stW[4], stA[2];
#pragma unroll
    for (int i = 0; i < 4; i++) stW[i] = swoff(r0 + 64 * i, c);
#pragma unroll
    for (int i = 0; i < 2; i++) stA[i] = swoff(r0 + 64 * i, c);

    float acc[4][8][4];
#pragma unroll
    for (int i = 0; i < 4; i++)
#pragma unroll
        for (int j = 0; j < 8; j++)
#pragma unroll
            for (int k = 0; k < 4; k++) acc[i][j][k] = 0.f;

    const uint32_t sW32 = (uint32_t)__cvta_generic_to_shared(sW);
    const uint32_t sA32 = (uint32_t)__cvta_generic_to_shared(sA);

    // ldmatrix lane address components
    const int aRow = lane & 15;                  // A row within 16-block
    const int aKC = (lane >> 4);                 // A k-chunk offset (0/1)
    const int bRow = (lane & 7) + ((lane >> 4) << 3);  // B n within 16-block
    const int bKC = ((lane >> 3) & 1);                 // B k-chunk offset (0/1)

    // precompute per-fragment row bases + xor terms
    uint32_t aBase[4];
    int aXor[4];
#pragma unroll
    for (int mf = 0; mf < 4; mf++) {
        int row = wm * 64 + mf * 16 + aRow;
        aBase[mf] = sA32 + (uint32_t)(row * 64);
        aXor[mf] = (row >> 1) & 3;
    }
    uint32_t bBase[4];
    int bXor[4];
#pragma unroll
    for (int nb = 0; nb < 4; nb++) {
        int row = wn * 64 + nb * 16 + bRow;
        bBase[nb] = sW32 + (uint32_t)(row * 64);
        bXor[nb] = (row >> 1) & 3;
    }

    uint4 rw[4], ra[2];
#pragma unroll
    for (int i = 0; i < 4; i++)
        rw[i] = *reinterpret_cast<const uint4*>(gW + (size_t)i * 64 * DDIM);
#pragma unroll
    for (int i = 0; i < 2; i++)
        ra[i] = *reinterpret_cast<const uint4*>(gA + (size_t)i * 64 * DDIM);

    for (int k0 = 0; k0 < DDIM; k0 += 32) {
        // commit prefetched chunk
#pragma unroll
        for (int i = 0; i < 4; i++)
            *reinterpret_cast<uint4*>(reinterpret_cast<char*>(sW) + stW[i]) = rw[i];
#pragma unroll
        for (int i = 0; i < 2; i++)
            *reinterpret_cast<uint4*>(reinterpret_cast<char*>(sA) + stA[i]) = ra[i];
        __syncthreads();

        // prefetch next chunk
        if (k0 + 32 < DDIM) {
            gW += 32;
            gA += 32;
#pragma unroll
            for (int i = 0; i < 4; i++)
                rw[i] = *reinterpret_cast<const uint4*>(gW + (size_t)i * 64 * DDIM);
#pragma unroll
            for (int i = 0; i < 2; i++)
                ra[i] = *reinterpret_cast<const uint4*>(gA + (size_t)i * 64 * DDIM);
        }

#pragma unroll
        for (int kk = 0; kk < 2; kk++) {  // two k16 steps
            const int kc = kk * 2;
            uint32_t b[8][2];
#pragma unroll
            for (int nb = 0; nb < 4; nb++) {
                uint32_t addr = bBase[nb] + (uint32_t)(((kc + bKC) ^ bXor[nb]) << 4);
                ldmat4(addr, b[nb * 2][0], b[nb * 2][1], b[nb * 2 + 1][0],
                       b[nb * 2 + 1][1]);
            }
            uint32_t a[4][4];
#pragma unroll
            for (int mf = 0; mf < 4; mf++) {
                uint32_t addr = aBase[mf] + (uint32_t)(((kc + aKC) ^ aXor[mf]) << 4);
                ldmat4(addr, a[mf][0], a[mf][1], a[mf][2], a[mf][3]);
            }
#pragma unroll
            for (int mf = 0; mf < 4; mf++)
#pragma unroll
                for (int nf = 0; nf < 8; nf++) mma16816(acc[mf][nf], a[mf], b[nf]);
        }
        __syncthreads();
    }

    // ---- epilogue ----
    const int gr = lane >> 2;
    const int tc2 = (lane & 3) * 2;
#pragma unroll
    for (int mf = 0; mf < 4; mf++) {
        const int row = t0 + wm * 64 + mf * 16 + gr;
#pragma unroll
        for (int nf = 0; nf < 8; nf++) {
            const int colL = wn * 64 + nf * 8 + tc2;
            const int col = o0 + colL;
            float bv0 = sBias[colL];
            float bv1 = sBias[colL + 1];
            float v00 = acc[mf][nf][0] + bv0;
            float v01 = acc[mf][nf][1] + bv1;
            float v10 = acc[mf][nf][2] + bv0;
            float v11 = acc[mf][nf][3] + bv1;
            if (LAYER == 0) {
                *reinterpret_cast<__half2*>(g_h + (size_t)row * DDIM + col) =
                    __floats2half2_rn(v00, v01);
                *reinterpret_cast<__half2*>(g_h + (size_t)(row + 8) * DDIM + col) =
                    __floats2half2_rn(v10, v11);
            } else {
                *reinterpret_cast<float2*>(outf + (size_t)row * DDIM + col) =
                    make_float2(v00, v01);
                *reinterpret_cast<float2*>(outf + (size_t)(row + 8) * DDIM + col) =
                    make_float2(v10, v11);
            }
        }
    }
}

extern "C" void kernel_launch(void* const* d_in, const int* in_sizes, int n_in,
                              void* d_out, int out_size) {
    const float* x = (const float*)d_in[0];
    const int* w1c = (const int*)d_in[1];
    const float* w1s = (const float*)d_in[2];
    const float* b1 = (const float*)d_in[3];
    const int* w2c = (const int*)d_in[4];
    const float* w2s = (const float*)d_in[5];
    const float* b2 = (const float*)d_in[6];
    float* out = (float*)d_out;

    const int dq_blocks = (DDIM * (size_t)DDIM / 4) / 256;
    dequant_kernel<<<dq_blocks, 256>>>(w1c, w1s, 0);
    dequant_kernel<<<dq_blocks, 256>>>(w2c, w2s, 1);

    const int sp_blocks = ((size_t)TDIM * DDIM / 4) / 256;
    split_kernel<<<sp_blocks, 256>>>(x);

    dim3 grid(DDIM / 256, TDIM / 128);
    gemm_kernel<0><<<grid, 256>>>(b1, nullptr);
    gemm_kernel<1><<<grid, 256>>>(b2, out);
}